// round 15
// baseline (speedup 1.0000x reference)
#include <cuda_runtime.h>
#include <cuda_fp16.h>
#include <cstdint>

#define B_    32
#define CIN_  256
#define COUT_ 256
#define H_    56
#define W_    56
#define HW_   3136
#define KDIM_ 2304
#define WPE_  (COUT_ * CIN_ * 9)

#define BM 128
#define BN 128
#define BK 32
#define NCHUNK 72
#define NSTAGE 6
#define WINDOW 3

// stage layout (16KB): A 8K (128 rows x 64B), B 8K (32 rows x 256B)
#define OFF_A 0
#define OFF_B 8192
#define STAGE 16384
#define DSMEM_BYTES (NSTAGE * STAGE + 1024)

// A tile rows 64B: swizzle bits[4:5] ^= bits[7:8]
#define SWA(o) ((o) ^ ((((o) >> 7) & 3) << 4))
// B tile rows 256B: swizzle bits[4:6] ^= bits[8:10]
#define SWB(o) ((o) ^ (((o) >> 4) & 0x70))

#define PLANE_N (B_ * CIN_ * HW_)
#define XPAD 128
#define PSTRIDE (PLANE_N + 2 * XPAD)

// ------------------------- scratch -------------------------
__device__ float g_pooled[B_ * CIN_];
__device__ __align__(16) __half g_aw[(size_t)B_ * COUT_ * KDIM_];
__device__ __align__(16) __half g_xplanes[3][PSTRIDE];

// ------------------------- helpers -------------------------
__device__ __forceinline__ uint32_t smem_u32(const void* p) {
    uint32_t a;
    asm("{ .reg .u64 t; cvta.to.shared.u64 t, %1; cvt.u32.u64 %0, t; }"
        : "=r"(a) : "l"(p));
    return a;
}

#define CP16(dst, src)                                                        \
    asm volatile("cp.async.cg.shared.global [%0], [%1], 16;"                  \
        :: "r"(dst), "l"(src) : "memory")
#define CP_COMMIT() asm volatile("cp.async.commit_group;" ::: "memory")
#define CP_WAIT(n)  asm volatile("cp.async.wait_group %0;" :: "n"(n) : "memory")

#define LDSM4(r, addr)                                                        \
    asm volatile("ldmatrix.sync.aligned.m8n8.x4.shared.b16 {%0,%1,%2,%3}, [%4];" \
        : "=r"((r)[0]), "=r"((r)[1]), "=r"((r)[2]), "=r"((r)[3]) : "r"(addr))

#define LDSM4T(r, addr)                                                       \
    asm volatile("ldmatrix.sync.aligned.m8n8.x4.trans.shared.b16 {%0,%1,%2,%3}, [%4];" \
        : "=r"((r)[0]), "=r"((r)[1]), "=r"((r)[2]), "=r"((r)[3]) : "r"(addr))

#define MMA(d, a, b0v, b1v)                                                   \
    asm volatile("mma.sync.aligned.m16n8k16.row.col.f32.f16.f16.f32 "         \
        "{%0,%1,%2,%3}, {%4,%5,%6,%7}, {%8,%9}, {%0,%1,%2,%3};"               \
        : "+f"((d)[0]), "+f"((d)[1]), "+f"((d)[2]), "+f"((d)[3])              \
        : "r"((a)[0]), "r"((a)[1]), "r"((a)[2]), "r"((a)[3]),                 \
          "r"(b0v), "r"(b1v))

// ------------------- kernel 1: x fp16 shift planes + pool -------------------
__global__ void xsplit_kernel(const float* __restrict__ x) {
    __shared__ unsigned short spk[HW_];
    __shared__ float rsm[8];
    int ci = blockIdx.x, b = blockIdx.y;
    int tid = threadIdx.x;
    size_t base = (size_t)(b * CIN_ + ci) * HW_;

    const float4* xr = (const float4*)(x + base);
    float s = 0.f;
    for (int i = tid; i < HW_ / 4; i += 256) {
        float4 v = xr[i];
        float vv[4] = {v.x, v.y, v.z, v.w};
        #pragma unroll
        for (int e = 0; e < 4; e++) {
            spk[i * 4 + e] = __half_as_ushort(__float2half_rn(vv[e]));
            s += vv[e];
        }
    }
    #pragma unroll
    for (int o = 16; o > 0; o >>= 1) s += __shfl_xor_sync(0xffffffffu, s, o);
    if ((tid & 31) == 0) rsm[tid >> 5] = s;
    __syncthreads();
    if (tid == 0) {
        float v = 0.f;
        #pragma unroll
        for (int i = 0; i < 8; i++) v += rsm[i];
        g_pooled[b * CIN_ + ci] = v * (1.f / (float)HW_);
    }

    for (int i4 = tid; i4 < HW_ / 4; i4 += 256) {
        int i0 = i4 * 4;
        unsigned short L[4], C[4], R[4];
        #pragma unroll
        for (int e = 0; e < 4; e++) {
            int i = i0 + e;
            int ow = i % W_;
            C[e] = spk[i];
            L[e] = (ow > 0) ? spk[i - 1] : (unsigned short)0;
            R[e] = (ow < W_ - 1) ? spk[i + 1] : (unsigned short)0;
        }
        size_t q = XPAD + base + i0;
        uint2 vL, vC, vR;
        vL.x = (uint32_t)L[0] | ((uint32_t)L[1] << 16);
        vL.y = (uint32_t)L[2] | ((uint32_t)L[3] << 16);
        vC.x = (uint32_t)C[0] | ((uint32_t)C[1] << 16);
        vC.y = (uint32_t)C[2] | ((uint32_t)C[3] << 16);
        vR.x = (uint32_t)R[0] | ((uint32_t)R[1] << 16);
        vR.y = (uint32_t)R[2] | ((uint32_t)R[3] << 16);
        *(uint2*)&g_xplanes[0][q] = vL;
        *(uint2*)&g_xplanes[1][q] = vC;
        *(uint2*)&g_xplanes[2][q] = vR;
    }
}

// ------- kernel 2: weight agg -> fp16, attention computed inline per block -------
__global__ void aggw_kernel(const float* __restrict__ weight,
                            const float* __restrict__ fc1_w,
                            const float* __restrict__ fc1_b,
                            const float* __restrict__ fc2_w,
                            const float* __restrict__ fc2_b) {
    __shared__ float a_sm[B_][4];
    __shared__ float l_sm[B_][4];
    __shared__ float att_sm[B_][4];
    int tid = threadIdx.x;

    // inline attention (threads 0..127 : (b, k) pairs, serial 256-MAC dots)
    if (tid < 128) {
        int b = tid >> 2, k = tid & 3;
        float s = fc1_b[k];
        const float* pb = g_pooled + b * CIN_;
        const float* wk = fc1_w + k * CIN_;
        #pragma unroll 8
        for (int c = 0; c < CIN_; c++) s += pb[c] * wk[c];
        a_sm[b][k] = fmaxf(s, 0.f);
    }
    __syncthreads();
    if (tid < 128) {
        int b = tid >> 2, k = tid & 3;
        float l = fc2_b[k];
        #pragma unroll
        for (int kk = 0; kk < 4; kk++) l += a_sm[b][kk] * fc2_w[k * 4 + kk];
        l_sm[b][k] = l;
    }
    __syncthreads();
    if (tid < 128) {
        int b = tid >> 2, k = tid & 3;
        float m = fmaxf(fmaxf(l_sm[b][0], l_sm[b][1]), fmaxf(l_sm[b][2], l_sm[b][3]));
        float e = expf(l_sm[b][k] - m);
        float sum = expf(l_sm[b][0] - m) + expf(l_sm[b][1] - m) +
                    expf(l_sm[b][2] - m) + expf(l_sm[b][3] - m);
        att_sm[b][k] = e / sum;
    }
    __syncthreads();

    int j = blockIdx.x * 256 + tid;           // float4 index into one expert
    const int Q = WPE_ / 4;
    const float4* w = (const float4*)weight;
    float4 w0 = w[0 * Q + j], w1 = w[1 * Q + j], w2 = w[2 * Q + j], w3 = w[3 * Q + j];

    uint2* dst = (uint2*)g_aw;
    #pragma unroll 4
    for (int b = 0; b < B_; b++) {
        float a0 = att_sm[b][0], a1 = att_sm[b][1];
        float a2 = att_sm[b][2], a3 = att_sm[b][3];
        float v0 = a0 * w0.x + a1 * w1.x + a2 * w2.x + a3 * w3.x;
        float v1 = a0 * w0.y + a1 * w1.y + a2 * w2.y + a3 * w3.y;
        float v2 = a0 * w0.z + a1 * w1.z + a2 * w2.z + a3 * w3.z;
        float v3 = a0 * w0.w + a1 * w1.w + a2 * w2.w + a3 * w3.w;
        uint2 o;
        o.x = (uint32_t)__half_as_ushort(__float2half_rn(v0)) |
              ((uint32_t)__half_as_ushort(__float2half_rn(v1)) << 16);
        o.y = (uint32_t)__half_as_ushort(__float2half_rn(v2)) |
              ((uint32_t)__half_as_ushort(__float2half_rn(v3)) << 16);
        dst[(size_t)b * Q + j] = o;
    }
}

// ----------- kernel 3: HMMA conv, 6-stage cp.async, 3-chunk windows -----------
// inline per-b attention for the bias; per-warp chunk rotation within windows
__global__ void __launch_bounds__(256, 2)
conv_kernel(const float* __restrict__ bias,
            const float* __restrict__ fc1_w,
            const float* __restrict__ fc1_b,
            const float* __restrict__ fc2_w,
            const float* __restrict__ fc2_b,
            float* __restrict__ out) {
    extern __shared__ char dsm[];
    __shared__ float bsm[BM];
    __shared__ float a_s[4];
    __shared__ float l_s[4];

    int tid = threadIdx.x, wid = tid >> 5, lane = tid & 31;
    int bx = blockIdx.x;
    int b = blockIdx.z, coBase = blockIdx.y * BM, pBase = bx * BN;
    int wm = wid >> 2, wn = wid & 3;

    uint32_t dbase = smem_u32(dsm);
    uint32_t abase = (dbase + 1023) & ~1023u;

    // ---- inline attention for this b (warps 0-3: k = wid) ----
    if (wid < 4) {
        const float* pb = g_pooled + b * CIN_;
        const float* wk = fc1_w + wid * CIN_;
        float s = 0.f;
        #pragma unroll
        for (int i = 0; i < 8; i++) s += pb[lane + 32 * i] * wk[lane + 32 * i];
        #pragma unroll
        for (int o = 16; o > 0; o >>= 1) s += __shfl_xor_sync(0xffffffffu, s, o);
        if (lane == 0) a_s[wid] = fmaxf(s + fc1_b[wid], 0.f);
    }
    __syncthreads();
    if (tid < 4) {
        float l = fc2_b[tid];
        #pragma unroll
        for (int kk = 0; kk < 4; kk++) l += a_s[kk] * fc2_w[tid * 4 + kk];
        l_s[tid] = l;
    }
    __syncthreads();
    if (tid < BM) {
        float m = fmaxf(fmaxf(l_s[0], l_s[1]), fmaxf(l_s[2], l_s[3]));
        float e0 = expf(l_s[0] - m), e1 = expf(l_s[1] - m);
        float e2 = expf(l_s[2] - m), e3 = expf(l_s[3] - m);
        float inv = 1.f / (e0 + e1 + e2 + e3);
        int co = coBase + tid;
        bsm[tid] = inv * (e0 * bias[0 * COUT_ + co] + e1 * bias[1 * COUT_ + co] +
                          e2 * bias[2 * COUT_ + co] + e3 * bias[3 * COUT_ + co]);
    }
    __syncthreads();

    const char* Ag = (const char*)g_aw + ((size_t)(b * COUT_ + coBase)) * KDIM_ * 2;
    size_t xoff = XPAD + (size_t)b * CIN_ * HW_;

    // fill geometry
    int fa_m = tid >> 1, fa_h = tid & 1;
    const char* fa_src = Ag + (size_t)fa_m * (KDIM_ * 2) + fa_h * 32;
    int fb_kr = tid >> 3, fb_j0 = (tid & 7) * 2;

    float acc[4][4][4];
    #pragma unroll
    for (int i = 0; i < 4; i++)
        #pragma unroll
        for (int j = 0; j < 4; j++)
            #pragma unroll
            for (int q = 0; q < 4; q++) acc[i][j][q] = 0.f;

    uint32_t rA[4];
    #pragma unroll
    for (int mi = 0; mi < 4; mi++)
        rA[mi] = (uint32_t)((wm * 64 + mi * 16 + (lane & 15)) * 64 + (lane >> 4) * 16);
    uint32_t sB[2];
    {
        int q = lane >> 3, sL = lane & 7;
        #pragma unroll
        for (int nh = 0; nh < 2; nh++)
            sB[nh] = SWB((uint32_t)(((q & 1) * 8 + sL) * 256 +
                                    (wn * 32 + nh * 16 + (q >> 1) * 8) * 2));
    }

    // ---- fill chunk c into stage s (order-independent: direct k decomposition) ----
    auto fill = [&](int s, int c) {
        uint32_t S = abase + s * STAGE;
        int k0 = c * BK;
        {
            const char* src = fa_src + k0 * 2;
            uint32_t rb = (uint32_t)(fa_m * 64 + fa_h * 32);
            #pragma unroll
            for (int j = 0; j < 2; j++)
                CP16(S + OFF_A + SWA(rb + j * 16), src + j * 16);
        }
        {
            int k = k0 + fb_kr;
            int ci = k / 9, rem = k - 9 * ci;     // const-div: mul-high, cheap
            int kh = rem / 3, kw = rem - 3 * kh;
            size_t e0 = xoff + (size_t)ci * HW_ + (kh - 1) * W_ + pBase;
            const char* sh = (const char*)(g_xplanes[kw] + e0);
            uint32_t rb = (uint32_t)(fb_kr * 256);
            #pragma unroll
            for (int jj = 0; jj < 2; jj++) {
                int j = fb_j0 + jj;
                CP16(S + OFF_B + SWB(rb + j * 16), sh + j * 16);
            }
        }
    };

    auto patch = [&](int s, int c) {
        if (bx != 0 && bx != 24) return;
        uint32_t S = abase + s * STAGE;
        int krow = lane;
        int k = c * BK + krow;
        int ci = k / 9, rem = k - 9 * ci;
        int kh = rem / 3;
        int w0 = wn * 32;
        int lo = 0, hi = 0;
        if (bx == 0 && kh == 0) { lo = w0; hi = min(w0 + 32, 56); }
        if (bx == 24 && kh == 2) { lo = max(w0, 8); hi = min(w0 + 32, 64); }
        for (int pl = lo; pl < hi; pl++) {
            uint32_t off = SWB((uint32_t)(krow * 256 + pl * 2));
            asm volatile("st.shared.u16 [%0], %1;" :: "r"(S + OFF_B + off),
                         "h"((unsigned short)0) : "memory");
        }
    };

    auto compute = [&](int s) {
        uint32_t S = abase + s * STAGE;
        uint32_t As = S + OFF_A, Bs = S + OFF_B;
        #pragma unroll
        for (int ks = 0; ks < 2; ks++) {
            uint32_t bh[2][4];
            #pragma unroll
            for (int nh = 0; nh < 2; nh++)
                LDSM4T(bh[nh], Bs + sB[nh] + (uint32_t)(ks * 4096));
            uint32_t ah[4][4];
            #pragma unroll
            for (int mi = 0; mi < 4; mi++)
                LDSM4(ah[mi], As + SWA(rA[mi] + (uint32_t)(ks * 32)));
            #pragma unroll
            for (int nh = 0; nh < 2; nh++)
                #pragma unroll
                for (int mi = 0; mi < 4; mi++)
                    #pragma unroll
                    for (int jn = 0; jn < 2; jn++)
                        MMA(acc[mi][nh * 2 + jn], ah[mi], bh[nh][jn * 2], bh[nh][jn * 2 + 1]);
        }
    };

    // per-warp chunk order within a window (spreads post-barrier LDSM burst)
    int rot = wid % 3;
    int ord0 = rot, ord1 = (rot + 1 == 3) ? 0 : rot + 1, ord2 = 3 - ord0 - ord1;
    int ord[3] = {ord0, ord1, ord2};

    // ---- pipeline: 6 stages, one sync per 3-chunk window (R10 interleaving) ----
    fill(0, 0); CP_COMMIT();
    fill(1, 1); CP_COMMIT();
    fill(2, 2); CP_COMMIT();

    for (int cw = 0; cw < NCHUNK; cw += WINDOW) {
        CP_WAIT(0);        // all outstanding fills (cw..cw+2) complete
        __syncthreads();   // visible to all warps; stages (cw-3..cw-1)%6 free
        #pragma unroll
        for (int u = 0; u < WINDOW; u++) {
            int c = cw + ord[u];
            int s = c % NSTAGE;
            patch(s, c);
            compute(s);
            int f = c + WINDOW;
            if (f < NCHUNK) { fill(f % NSTAGE, f); CP_COMMIT(); }
        }
    }

    // ---- epilogue ----
    int r0 = wm * 64 + (lane >> 2);
    #pragma unroll
    for (int mi = 0; mi < 4; mi++) {
        int row = r0 + mi * 16;
        float b0 = bsm[row], b1 = bsm[row + 8];
        float* o0 = out + ((size_t)(b * COUT_ + coBase + row)) * HW_;
        float* o1 = o0 + 8 * HW_;
        #pragma unroll
        for (int j = 0; j < 4; j++) {
            int p = pBase + wn * 32 + j * 8 + (lane & 3) * 2;
            if (p < HW_) {
                float2 v0 = make_float2(acc[mi][j][0] + b0, acc[mi][j][1] + b0);
                float2 v1 = make_float2(acc[mi][j][2] + b1, acc[mi][j][3] + b1);
                *(float2*)(o0 + p) = v0;
                *(float2*)(o1 + p) = v1;
            }
        }
    }
}

// ------------------------- launch -------------------------
extern "C" void kernel_launch(void* const* d_in, const int* in_sizes, int n_in,
                              void* d_out, int out_size) {
    const float* x      = (const float*)d_in[0];
    const float* weight = (const float*)d_in[1];
    const float* bias   = (const float*)d_in[2];
    const float* fc1_w  = (const float*)d_in[3];
    const float* fc1_b  = (const float*)d_in[4];
    const float* fc2_w  = (const float*)d_in[5];
    const float* fc2_b  = (const float*)d_in[6];
    float* out = (float*)d_out;

    cudaFuncSetAttribute(conv_kernel,
                         cudaFuncAttributeMaxDynamicSharedMemorySize, DSMEM_BYTES);

    xsplit_kernel<<<dim3(CIN_, B_), 256>>>(x);
    aggw_kernel<<<WPE_ / 4 / 256, 256>>>(weight, fc1_w, fc1_b, fc2_w, fc2_b);
    conv_kernel<<<dim3((HW_ + BN - 1) / BN, COUT_ / BM, B_), 256, DSMEM_BYTES>>>(
        bias, fc1_w, fc1_b, fc2_w, fc2_b, out);
}

// round 16
// speedup vs baseline: 1.0649x; 1.0649x over previous
#include <cuda_runtime.h>
#include <cuda_fp16.h>
#include <cstdint>

#define B_    32
#define CIN_  256
#define COUT_ 256
#define H_    56
#define W_    56
#define HW_   3136
#define KDIM_ 2304
#define WPE_  (COUT_ * CIN_ * 9)

#define BM 128
#define BN 128
#define BK 32
#define NCHUNK 72
#define NSTAGE 6
#define WINDOW 3

// stage layout (16KB): A 8K (128 rows x 64B), B 8K (32 rows x 256B)
#define OFF_A 0
#define OFF_B 8192
#define STAGE 16384
#define DSMEM_BYTES (NSTAGE * STAGE + 1024)

// A tile rows 64B: swizzle bits[4:5] ^= bits[7:8]
#define SWA(o) ((o) ^ ((((o) >> 7) & 3) << 4))
// B tile rows 256B: swizzle bits[4:6] ^= bits[8:10]
#define SWB(o) ((o) ^ (((o) >> 4) & 0x70))

#define PLANE_N (B_ * CIN_ * HW_)
#define XPAD 128
#define PSTRIDE (PLANE_N + 2 * XPAD)

// ------------------------- scratch -------------------------
__device__ float g_pooled[B_ * CIN_];
__device__ __align__(16) __half g_aw[(size_t)B_ * COUT_ * KDIM_];
__device__ __align__(16) __half g_xplanes[3][PSTRIDE];

// ------------------------- helpers -------------------------
__device__ __forceinline__ uint32_t smem_u32(const void* p) {
    uint32_t a;
    asm("{ .reg .u64 t; cvta.to.shared.u64 t, %1; cvt.u32.u64 %0, t; }"
        : "=r"(a) : "l"(p));
    return a;
}

#define CP16(dst, src)                                                        \
    asm volatile("cp.async.cg.shared.global [%0], [%1], 16;"                  \
        :: "r"(dst), "l"(src) : "memory")
#define CP_COMMIT() asm volatile("cp.async.commit_group;" ::: "memory")
#define CP_WAIT(n)  asm volatile("cp.async.wait_group %0;" :: "n"(n) : "memory")

#define LDSM4(r, addr)                                                        \
    asm volatile("ldmatrix.sync.aligned.m8n8.x4.shared.b16 {%0,%1,%2,%3}, [%4];" \
        : "=r"((r)[0]), "=r"((r)[1]), "=r"((r)[2]), "=r"((r)[3]) : "r"(addr))

#define LDSM4T(r, addr)                                                       \
    asm volatile("ldmatrix.sync.aligned.m8n8.x4.trans.shared.b16 {%0,%1,%2,%3}, [%4];" \
        : "=r"((r)[0]), "=r"((r)[1]), "=r"((r)[2]), "=r"((r)[3]) : "r"(addr))

#define MMA(d, a, b0v, b1v)                                                   \
    asm volatile("mma.sync.aligned.m16n8k16.row.col.f32.f16.f16.f32 "         \
        "{%0,%1,%2,%3}, {%4,%5,%6,%7}, {%8,%9}, {%0,%1,%2,%3};"               \
        : "+f"((d)[0]), "+f"((d)[1]), "+f"((d)[2]), "+f"((d)[3])              \
        : "r"((a)[0]), "r"((a)[1]), "r"((a)[2]), "r"((a)[3]),                 \
          "r"(b0v), "r"(b1v))

// ------------------- kernel 1: x fp16 shift planes + pool -------------------
// W = 56 -> 14 four-pixel groups per row; groups never straddle rows.
__global__ void xsplit_kernel(const float* __restrict__ x) {
    __shared__ unsigned short spk[HW_];
    __shared__ float rsm[8];
    int ci = blockIdx.x, b = blockIdx.y;
    int tid = threadIdx.x;
    size_t base = (size_t)(b * CIN_ + ci) * HW_;

    const float4* xr = (const float4*)(x + base);
    float s = 0.f;
    for (int i = tid; i < HW_ / 4; i += 256) {
        float4 v = xr[i];
        float vv[4] = {v.x, v.y, v.z, v.w};
        #pragma unroll
        for (int e = 0; e < 4; e++) {
            spk[i * 4 + e] = __half_as_ushort(__float2half_rn(vv[e]));
            s += vv[e];
        }
    }
    #pragma unroll
    for (int o = 16; o > 0; o >>= 1) s += __shfl_xor_sync(0xffffffffu, s, o);
    if ((tid & 31) == 0) rsm[tid >> 5] = s;
    __syncthreads();
    if (tid == 0) {
        float v = 0.f;
        #pragma unroll
        for (int i = 0; i < 8; i++) v += rsm[i];
        g_pooled[b * CIN_ + ci] = v * (1.f / (float)HW_);
    }

    // one 4-pixel group per iter: 2 aligned 32-bit smem loads + funnel shifts
    const uint32_t* spk32 = (const uint32_t*)spk;
    for (int i4 = tid; i4 < HW_ / 4; i4 += 256) {
        int g = i4 % 14;                  // group index within row
        int i0 = i4 * 4;
        uint32_t c0 = spk32[i4 * 2], c1 = spk32[i4 * 2 + 1];
        uint32_t prev = (g > 0)  ? (uint32_t)spk[i0 - 1] : 0u;   // pixel i0-1
        uint32_t next = (g < 13) ? (uint32_t)spk[i0 + 4] : 0u;   // pixel i0+4
        uint2 vC = make_uint2(c0, c1);
        uint2 vL, vR;
        vL.x = (c0 << 16) | prev;                 // [i0-1, i0]
        vL.y = __funnelshift_l(c0 >> 16, c1 << 16, 16); // hmm: want [i0+1, i0+2]
        vL.y = (c0 >> 16) | (c1 << 16);           // [i0+1, i0+2]
        vR.x = (c0 >> 16) | (c1 << 16);           // [i0+1, i0+2]
        vR.y = (c1 >> 16) | (next << 16);         // [i0+3, i0+4]
        size_t q = XPAD + base + i0;
        *(uint2*)&g_xplanes[0][q] = vL;
        *(uint2*)&g_xplanes[1][q] = vC;
        *(uint2*)&g_xplanes[2][q] = vR;
    }
}

// ------- kernel 2: weight agg -> fp16, attention computed inline per block -------
__global__ void aggw_kernel(const float* __restrict__ weight,
                            const float* __restrict__ fc1_w,
                            const float* __restrict__ fc1_b,
                            const float* __restrict__ fc2_w,
                            const float* __restrict__ fc2_b) {
    __shared__ float a_sm[B_][4];
    __shared__ float l_sm[B_][4];
    __shared__ float att_sm[B_][4];
    int tid = threadIdx.x;

    if (tid < 128) {
        int b = tid >> 2, k = tid & 3;
        float s = fc1_b[k];
        const float* pb = g_pooled + b * CIN_;
        const float* wk = fc1_w + k * CIN_;
        #pragma unroll 8
        for (int c = 0; c < CIN_; c++) s += pb[c] * wk[c];
        a_sm[b][k] = fmaxf(s, 0.f);
    }
    __syncthreads();
    if (tid < 128) {
        int b = tid >> 2, k = tid & 3;
        float l = fc2_b[k];
        #pragma unroll
        for (int kk = 0; kk < 4; kk++) l += a_sm[b][kk] * fc2_w[k * 4 + kk];
        l_sm[b][k] = l;
    }
    __syncthreads();
    if (tid < 128) {
        int b = tid >> 2, k = tid & 3;
        float m = fmaxf(fmaxf(l_sm[b][0], l_sm[b][1]), fmaxf(l_sm[b][2], l_sm[b][3]));
        float e = expf(l_sm[b][k] - m);
        float sum = expf(l_sm[b][0] - m) + expf(l_sm[b][1] - m) +
                    expf(l_sm[b][2] - m) + expf(l_sm[b][3] - m);
        att_sm[b][k] = e / sum;
    }
    __syncthreads();

    int j = blockIdx.x * 256 + tid;
    const int Q = WPE_ / 4;
    const float4* w = (const float4*)weight;
    float4 w0 = w[0 * Q + j], w1 = w[1 * Q + j], w2 = w[2 * Q + j], w3 = w[3 * Q + j];

    uint2* dst = (uint2*)g_aw;
    #pragma unroll 4
    for (int b = 0; b < B_; b++) {
        float a0 = att_sm[b][0], a1 = att_sm[b][1];
        float a2 = att_sm[b][2], a3 = att_sm[b][3];
        float v0 = a0 * w0.x + a1 * w1.x + a2 * w2.x + a3 * w3.x;
        float v1 = a0 * w0.y + a1 * w1.y + a2 * w2.y + a3 * w3.y;
        float v2 = a0 * w0.z + a1 * w1.z + a2 * w2.z + a3 * w3.z;
        float v3 = a0 * w0.w + a1 * w1.w + a2 * w2.w + a3 * w3.w;
        uint2 o;
        o.x = (uint32_t)__half_as_ushort(__float2half_rn(v0)) |
              ((uint32_t)__half_as_ushort(__float2half_rn(v1)) << 16);
        o.y = (uint32_t)__half_as_ushort(__float2half_rn(v2)) |
              ((uint32_t)__half_as_ushort(__float2half_rn(v3)) << 16);
        dst[(size_t)b * Q + j] = o;
    }
}

// ----------- kernel 3: HMMA conv — hot loop byte-identical to R13 -----------
__global__ void __launch_bounds__(256, 2)
conv_kernel(const float* __restrict__ bias,
            const float* __restrict__ fc1_w,
            const float* __restrict__ fc1_b,
            const float* __restrict__ fc2_w,
            const float* __restrict__ fc2_b,
            float* __restrict__ out) {
    extern __shared__ char dsm[];
    __shared__ float bsm[BM];
    __shared__ float a_s[4];
    __shared__ float l_s[4];

    int tid = threadIdx.x, wid = tid >> 5, lane = tid & 31;
    int bx = blockIdx.x;
    int b = blockIdx.z, coBase = blockIdx.y * BM, pBase = bx * BN;
    int wm = wid >> 2, wn = wid & 3;

    uint32_t dbase = smem_u32(dsm);
    uint32_t abase = (dbase + 1023) & ~1023u;

    // ---- inline attention for this b (prologue only, outside hot loop) ----
    if (wid < 4) {
        const float* pb = g_pooled + b * CIN_;
        const float* wk = fc1_w + wid * CIN_;
        float s = 0.f;
        #pragma unroll
        for (int i = 0; i < 8; i++) s += pb[lane + 32 * i] * wk[lane + 32 * i];
        #pragma unroll
        for (int o = 16; o > 0; o >>= 1) s += __shfl_xor_sync(0xffffffffu, s, o);
        if (lane == 0) a_s[wid] = fmaxf(s + fc1_b[wid], 0.f);
    }
    __syncthreads();
    if (tid < 4) {
        float l = fc2_b[tid];
        #pragma unroll
        for (int kk = 0; kk < 4; kk++) l += a_s[kk] * fc2_w[tid * 4 + kk];
        l_s[tid] = l;
    }
    __syncthreads();
    if (tid < BM) {
        float m = fmaxf(fmaxf(l_s[0], l_s[1]), fmaxf(l_s[2], l_s[3]));
        float e0 = expf(l_s[0] - m), e1 = expf(l_s[1] - m);
        float e2 = expf(l_s[2] - m), e3 = expf(l_s[3] - m);
        float inv = 1.f / (e0 + e1 + e2 + e3);
        int co = coBase + tid;
        bsm[tid] = inv * (e0 * bias[0 * COUT_ + co] + e1 * bias[1 * COUT_ + co] +
                          e2 * bias[2 * COUT_ + co] + e3 * bias[3 * COUT_ + co]);
    }
    __syncthreads();

    const char* Ag = (const char*)g_aw + ((size_t)(b * COUT_ + coBase)) * KDIM_ * 2;
    size_t xoff = XPAD + (size_t)b * CIN_ * HW_;

    int fa_m = tid >> 1, fa_h = tid & 1;
    const char* fa_src = Ag + (size_t)fa_m * (KDIM_ * 2) + fa_h * 32;
    int fb_kr = tid >> 3, fb_j0 = (tid & 7) * 2;
    int fb_ci = fb_kr / 9;
    int fb_rem = fb_kr - 9 * fb_ci;

    float acc[4][4][4];
    #pragma unroll
    for (int i = 0; i < 4; i++)
        #pragma unroll
        for (int j = 0; j < 4; j++)
            #pragma unroll
            for (int q = 0; q < 4; q++) acc[i][j][q] = 0.f;

    uint32_t rA[4];
    #pragma unroll
    for (int mi = 0; mi < 4; mi++)
        rA[mi] = (uint32_t)((wm * 64 + mi * 16 + (lane & 15)) * 64 + (lane >> 4) * 16);
    uint32_t sB[2];
    {
        int q = lane >> 3, sL = lane & 7;
        #pragma unroll
        for (int nh = 0; nh < 2; nh++)
            sB[nh] = SWB((uint32_t)(((q & 1) * 8 + sL) * 256 +
                                    (wn * 32 + nh * 16 + (q >> 1) * 8) * 2));
    }

    auto fill = [&](int s, int c) {
        uint32_t S = abase + s * STAGE;
        int k0 = c * BK;
        {
            const char* src = fa_src + k0 * 2;
            uint32_t rb = (uint32_t)(fa_m * 64 + fa_h * 32);
            #pragma unroll
            for (int j = 0; j < 2; j++)
                CP16(S + OFF_A + SWA(rb + j * 16), src + j * 16);
        }
        {
            int kh = fb_rem / 3, kw = fb_rem - 3 * (fb_rem / 3);
            size_t e0 = xoff + (size_t)fb_ci * HW_ + (kh - 1) * W_ + pBase;
            const char* sh = (const char*)(g_xplanes[kw] + e0);
            uint32_t rb = (uint32_t)(fb_kr * 256);
            #pragma unroll
            for (int jj = 0; jj < 2; jj++) {
                int j = fb_j0 + jj;
                CP16(S + OFF_B + SWB(rb + j * 16), sh + j * 16);
            }
        }
        fb_ci += 3; fb_rem += 5;
        if (fb_rem >= 9) { fb_rem -= 9; fb_ci += 1; }
    };

    auto patch = [&](int s, int c) {
        if (bx != 0 && bx != 24) return;
        uint32_t S = abase + s * STAGE;
        int krow = lane;
        int k = c * BK + krow;
        int ci = k / 9, rem = k - 9 * ci;
        int kh = rem / 3;
        int w0 = wn * 32;
        int lo = 0, hi = 0;
        if (bx == 0 && kh == 0) { lo = w0; hi = min(w0 + 32, 56); }
        if (bx == 24 && kh == 2) { lo = max(w0, 8); hi = min(w0 + 32, 64); }
        for (int pl = lo; pl < hi; pl++) {
            uint32_t off = SWB((uint32_t)(krow * 256 + pl * 2));
            asm volatile("st.shared.u16 [%0], %1;" :: "r"(S + OFF_B + off),
                         "h"((unsigned short)0) : "memory");
        }
    };

    auto compute = [&](int s) {
        uint32_t S = abase + s * STAGE;
        uint32_t As = S + OFF_A, Bs = S + OFF_B;
        #pragma unroll
        for (int ks = 0; ks < 2; ks++) {
            uint32_t bh[2][4];
            #pragma unroll
            for (int nh = 0; nh < 2; nh++)
                LDSM4T(bh[nh], Bs + sB[nh] + (uint32_t)(ks * 4096));
            uint32_t ah[4][4];
            #pragma unroll
            for (int mi = 0; mi < 4; mi++)
                LDSM4(ah[mi], As + SWA(rA[mi] + (uint32_t)(ks * 32)));
            #pragma unroll
            for (int nh = 0; nh < 2; nh++)
                #pragma unroll
                for (int mi = 0; mi < 4; mi++)
                    #pragma unroll
                    for (int jn = 0; jn < 2; jn++)
                        MMA(acc[mi][nh * 2 + jn], ah[mi], bh[nh][jn * 2], bh[nh][jn * 2 + 1]);
        }
    };

    // ---- pipeline: 6 stages, one sync per 3-chunk window (R13 order, NO rotation) ----
    fill(0, 0); CP_COMMIT();
    fill(1, 1); CP_COMMIT();
    fill(2, 2); CP_COMMIT();

    for (int cw = 0; cw < NCHUNK; cw += WINDOW) {
        CP_WAIT(0);
        __syncthreads();
        #pragma unroll
        for (int u = 0; u < WINDOW; u++) {
            int c = cw + u;
            int s = c % NSTAGE;
            patch(s, c);
            compute(s);
            int f = c + WINDOW;
            if (f < NCHUNK) { fill(f % NSTAGE, f); CP_COMMIT(); }
        }
    }

    // ---- epilogue ----
    int r0 = wm * 64 + (lane >> 2);
    #pragma unroll
    for (int mi = 0; mi < 4; mi++) {
        int row = r0 + mi * 16;
        float b0 = bsm[row], b1 = bsm[row + 8];
        float* o0 = out + ((size_t)(b * COUT_ + coBase + row)) * HW_;
        float* o1 = o0 + 8 * HW_;
        #pragma unroll
        for (int j = 0; j < 4; j++) {
            int p = pBase + wn * 32 + j * 8 + (lane & 3) * 2;
            if (p < HW_) {
                float2 v0 = make_float2(acc[mi][j][0] + b0, acc[mi][j][1] + b0);
                float2 v1 = make_float2(acc[mi][j][2] + b1, acc[mi][j][3] + b1);
                *(float2*)(o0 + p) = v0;
                *(float2*)(o1 + p) = v1;
            }
        }
    }
}

// ------------------------- launch -------------------------
extern "C" void kernel_launch(void* const* d_in, const int* in_sizes, int n_in,
                              void* d_out, int out_size) {
    const float* x      = (const float*)d_in[0];
    const float* weight = (const float*)d_in[1];
    const float* bias   = (const float*)d_in[2];
    const float* fc1_w  = (const float*)d_in[3];
    const float* fc1_b  = (const float*)d_in[4];
    const float* fc2_w  = (const float*)d_in[5];
    const float* fc2_b  = (const float*)d_in[6];
    float* out = (float*)d_out;

    cudaFuncSetAttribute(conv_kernel,
                         cudaFuncAttributeMaxDynamicSharedMemorySize, DSMEM_BYTES);

    xsplit_kernel<<<dim3(CIN_, B_), 256>>>(x);
    aggw_kernel<<<WPE_ / 4 / 256, 256>>>(weight, fc1_w, fc1_b, fc2_w, fc2_b);
    conv_kernel<<<dim3((HW_ + BN - 1) / BN, COUT_ / BM, B_), 256, DSMEM_BYTES>>>(
        bias, fc1_w, fc1_b, fc2_w, fc2_b, out);
}

// round 17
// speedup vs baseline: 1.1115x; 1.0438x over previous
#include <cuda_runtime.h>
#include <cuda_fp16.h>
#include <cstdint>

#define B_    32
#define CIN_  256
#define COUT_ 256
#define H_    56
#define W_    56
#define HW_   3136
#define KDIM_ 2304
#define WPE_  (COUT_ * CIN_ * 9)

#define BM 128
#define BN 128
#define BK 32
#define NCHUNK 72
#define NSTAGE 6
#define WINDOW 3

// stage layout (16KB): A 8K (128 rows x 64B), B 8K (32 rows x 256B)
#define OFF_A 0
#define OFF_B 8192
#define STAGE 16384
#define DSMEM_BYTES (NSTAGE * STAGE + 1024)

// A tile rows 64B: swizzle bits[4:5] ^= bits[7:8]
#define SWA(o) ((o) ^ ((((o) >> 7) & 3) << 4))
// B tile rows 256B: swizzle bits[4:6] ^= bits[8:10]
#define SWB(o) ((o) ^ (((o) >> 4) & 0x70))

#define PLANE_N (B_ * CIN_ * HW_)
#define XPAD 128
#define PSTRIDE (PLANE_N + 2 * XPAD)

// ------------------------- scratch -------------------------
__device__ float g_pooled[B_ * CIN_];
__device__ float g_att[B_ * 4];
__device__ __align__(16) __half g_aw[(size_t)B_ * COUT_ * KDIM_];
__device__ __align__(16) __half g_xplanes[3][PSTRIDE];

// ------------------------- helpers -------------------------
__device__ __forceinline__ uint32_t smem_u32(const void* p) {
    uint32_t a;
    asm("{ .reg .u64 t; cvta.to.shared.u64 t, %1; cvt.u32.u64 %0, t; }"
        : "=r"(a) : "l"(p));
    return a;
}

#define CP16(dst, src)                                                        \
    asm volatile("cp.async.cg.shared.global [%0], [%1], 16;"                  \
        :: "r"(dst), "l"(src) : "memory")
#define CP_COMMIT() asm volatile("cp.async.commit_group;" ::: "memory")
#define CP_WAIT(n)  asm volatile("cp.async.wait_group %0;" :: "n"(n) : "memory")

#define LDSM4(r, addr)                                                        \
    asm volatile("ldmatrix.sync.aligned.m8n8.x4.shared.b16 {%0,%1,%2,%3}, [%4];" \
        : "=r"((r)[0]), "=r"((r)[1]), "=r"((r)[2]), "=r"((r)[3]) : "r"(addr))

#define LDSM4T(r, addr)                                                       \
    asm volatile("ldmatrix.sync.aligned.m8n8.x4.trans.shared.b16 {%0,%1,%2,%3}, [%4];" \
        : "=r"((r)[0]), "=r"((r)[1]), "=r"((r)[2]), "=r"((r)[3]) : "r"(addr))

#define MMA(d, a, b0v, b1v)                                                   \
    asm volatile("mma.sync.aligned.m16n8k16.row.col.f32.f16.f16.f32 "         \
        "{%0,%1,%2,%3}, {%4,%5,%6,%7}, {%8,%9}, {%0,%1,%2,%3};"               \
        : "+f"((d)[0]), "+f"((d)[1]), "+f"((d)[2]), "+f"((d)[3])              \
        : "r"((a)[0]), "r"((a)[1]), "r"((a)[2]), "r"((a)[3]),                 \
          "r"(b0v), "r"(b1v))

// ------------------- kernel 1: x fp16 shift planes + pool -------------------
// W = 56 -> 14 four-pixel groups per row; groups never straddle rows.
__global__ void xsplit_kernel(const float* __restrict__ x) {
    __shared__ unsigned short spk[HW_];
    __shared__ float rsm[8];
    int ci = blockIdx.x, b = blockIdx.y;
    int tid = threadIdx.x;
    size_t base = (size_t)(b * CIN_ + ci) * HW_;

    const float4* xr = (const float4*)(x + base);
    float s = 0.f;
    for (int i = tid; i < HW_ / 4; i += 256) {
        float4 v = xr[i];
        float vv[4] = {v.x, v.y, v.z, v.w};
        #pragma unroll
        for (int e = 0; e < 4; e++) {
            spk[i * 4 + e] = __half_as_ushort(__float2half_rn(vv[e]));
            s += vv[e];
        }
    }
    #pragma unroll
    for (int o = 16; o > 0; o >>= 1) s += __shfl_xor_sync(0xffffffffu, s, o);
    if ((tid & 31) == 0) rsm[tid >> 5] = s;
    __syncthreads();
    if (tid == 0) {
        float v = 0.f;
        #pragma unroll
        for (int i = 0; i < 8; i++) v += rsm[i];
        g_pooled[b * CIN_ + ci] = v * (1.f / (float)HW_);
    }

    // one 4-pixel group per iter: 2 aligned 32-bit smem loads + shifts
    const uint32_t* spk32 = (const uint32_t*)spk;
    for (int i4 = tid; i4 < HW_ / 4; i4 += 256) {
        int g = i4 % 14;                  // group index within row
        int i0 = i4 * 4;
        uint32_t c0 = spk32[i4 * 2], c1 = spk32[i4 * 2 + 1];
        uint32_t prev = (g > 0)  ? (uint32_t)spk[i0 - 1] : 0u;   // pixel i0-1
        uint32_t next = (g < 13) ? (uint32_t)spk[i0 + 4] : 0u;   // pixel i0+4
        uint2 vC = make_uint2(c0, c1);
        uint2 vL, vR;
        uint32_t mid = (c0 >> 16) | (c1 << 16);   // [i0+1, i0+2]
        vL.x = (c0 << 16) | prev;                 // [i0-1, i0]
        vL.y = mid;
        vR.x = mid;
        vR.y = (c1 >> 16) | (next << 16);         // [i0+3, i0+4]
        size_t q = XPAD + base + i0;
        *(uint2*)&g_xplanes[0][q] = vL;
        *(uint2*)&g_xplanes[1][q] = vC;
        *(uint2*)&g_xplanes[2][q] = vR;
    }
}

// ------------------------- kernel 2: attention -------------------------
__global__ void attn_kernel(const float* __restrict__ fc1_w,
                            const float* __restrict__ fc1_b,
                            const float* __restrict__ fc2_w,
                            const float* __restrict__ fc2_b) {
    __shared__ float a_sm[B_][4];
    __shared__ float l_sm[B_][4];
    int tid = threadIdx.x;
    int b = tid >> 2, k = tid & 3;

    float s = 0.f;
    const float* pb = g_pooled + b * CIN_;
    const float* wk = fc1_w + k * CIN_;
    for (int c = 0; c < CIN_; c++) s += pb[c] * wk[c];
    s += fc1_b[k];
    a_sm[b][k] = fmaxf(s, 0.f);
    __syncthreads();

    float l = fc2_b[k];
    #pragma unroll
    for (int kk = 0; kk < 4; kk++) l += a_sm[b][kk] * fc2_w[k * 4 + kk];
    l_sm[b][k] = l;
    __syncthreads();

    float m = fmaxf(fmaxf(l_sm[b][0], l_sm[b][1]), fmaxf(l_sm[b][2], l_sm[b][3]));
    float e = expf(l_sm[b][k] - m);
    float sum = expf(l_sm[b][0] - m) + expf(l_sm[b][1] - m) +
                expf(l_sm[b][2] - m) + expf(l_sm[b][3] - m);
    g_att[b * 4 + k] = e / sum;
}

// --------- kernel 3: weight agg -> fp16 (read weights ONCE, loop over b) ---------
__global__ void aggw_kernel(const float* __restrict__ weight) {
    __shared__ float att_sm[B_][4];
    int tid = threadIdx.x;
    if (tid < B_ * 4) ((float*)att_sm)[tid] = g_att[tid];
    __syncthreads();

    int j = blockIdx.x * 256 + tid;           // float4 index into one expert
    const int Q = WPE_ / 4;                   // 147456
    const float4* w = (const float4*)weight;
    float4 w0 = w[0 * Q + j], w1 = w[1 * Q + j], w2 = w[2 * Q + j], w3 = w[3 * Q + j];

    uint2* dst = (uint2*)g_aw;
    #pragma unroll 4
    for (int b = 0; b < B_; b++) {
        float a0 = att_sm[b][0], a1 = att_sm[b][1];
        float a2 = att_sm[b][2], a3 = att_sm[b][3];
        float v0 = a0 * w0.x + a1 * w1.x + a2 * w2.x + a3 * w3.x;
        float v1 = a0 * w0.y + a1 * w1.y + a2 * w2.y + a3 * w3.y;
        float v2 = a0 * w0.z + a1 * w1.z + a2 * w2.z + a3 * w3.z;
        float v3 = a0 * w0.w + a1 * w1.w + a2 * w2.w + a3 * w3.w;
        uint2 o;
        o.x = (uint32_t)__half_as_ushort(__float2half_rn(v0)) |
              ((uint32_t)__half_as_ushort(__float2half_rn(v1)) << 16);
        o.y = (uint32_t)__half_as_ushort(__float2half_rn(v2)) |
              ((uint32_t)__half_as_ushort(__float2half_rn(v3)) << 16);
        dst[(size_t)b * Q + j] = o;
    }
}

// ----------- kernel 4: HMMA conv, 6-stage cp.async, 3-chunk windows -----------
// (byte-identical to R13 — the proven 350.4us configuration)
__global__ void __launch_bounds__(256, 2)
conv_kernel(const float* __restrict__ bias, float* __restrict__ out) {
    extern __shared__ char dsm[];
    __shared__ float bsm[BM];

    int tid = threadIdx.x, wid = tid >> 5, lane = tid & 31;
    int bx = blockIdx.x;
    int b = blockIdx.z, coBase = blockIdx.y * BM, pBase = bx * BN;
    int wm = wid >> 2, wn = wid & 3;

    uint32_t dbase = smem_u32(dsm);
    uint32_t abase = (dbase + 1023) & ~1023u;

    if (tid < BM) {
        float a0 = g_att[b * 4 + 0], a1 = g_att[b * 4 + 1];
        float a2 = g_att[b * 4 + 2], a3 = g_att[b * 4 + 3];
        int co = coBase + tid;
        bsm[tid] = a0 * bias[0 * COUT_ + co] + a1 * bias[1 * COUT_ + co] +
                   a2 * bias[2 * COUT_ + co] + a3 * bias[3 * COUT_ + co];
    }
    __syncthreads();

    const char* Ag = (const char*)g_aw + ((size_t)(b * COUT_ + coBase)) * KDIM_ * 2;
    size_t xoff = XPAD + (size_t)b * CIN_ * HW_;

    // fill geometry
    int fa_m = tid >> 1, fa_h = tid & 1;
    const char* fa_src = Ag + (size_t)fa_m * (KDIM_ * 2) + fa_h * 32;
    int fb_kr = tid >> 3, fb_j0 = (tid & 7) * 2;
    int fb_ci = fb_kr / 9;
    int fb_rem = fb_kr - 9 * fb_ci;

    float acc[4][4][4];
    #pragma unroll
    for (int i = 0; i < 4; i++)
        #pragma unroll
        for (int j = 0; j < 4; j++)
            #pragma unroll
            for (int q = 0; q < 4; q++) acc[i][j][q] = 0.f;

    uint32_t rA[4];
    #pragma unroll
    for (int mi = 0; mi < 4; mi++)
        rA[mi] = (uint32_t)((wm * 64 + mi * 16 + (lane & 15)) * 64 + (lane >> 4) * 16);
    uint32_t sB[2];
    {
        int q = lane >> 3, sL = lane & 7;
        #pragma unroll
        for (int nh = 0; nh < 2; nh++)
            sB[nh] = SWB((uint32_t)(((q & 1) * 8 + sL) * 256 +
                                    (wn * 32 + nh * 16 + (q >> 1) * 8) * 2));
    }

    auto fill = [&](int s, int c) {
        uint32_t S = abase + s * STAGE;
        int k0 = c * BK;
        {
            const char* src = fa_src + k0 * 2;
            uint32_t rb = (uint32_t)(fa_m * 64 + fa_h * 32);
            #pragma unroll
            for (int j = 0; j < 2; j++)
                CP16(S + OFF_A + SWA(rb + j * 16), src + j * 16);
        }
        {
            int kh = fb_rem / 3, kw = fb_rem - 3 * (fb_rem / 3);
            size_t e0 = xoff + (size_t)fb_ci * HW_ + (kh - 1) * W_ + pBase;
            const char* sh = (const char*)(g_xplanes[kw] + e0);
            uint32_t rb = (uint32_t)(fb_kr * 256);
            #pragma unroll
            for (int jj = 0; jj < 2; jj++) {
                int j = fb_j0 + jj;
                CP16(S + OFF_B + SWB(rb + j * 16), sh + j * 16);
            }
        }
        fb_ci += 3; fb_rem += 5;
        if (fb_rem >= 9) { fb_rem -= 9; fb_ci += 1; }
    };

    auto patch = [&](int s, int c) {
        if (bx != 0 && bx != 24) return;
        uint32_t S = abase + s * STAGE;
        int krow = lane;
        int k = c * BK + krow;
        int ci = k / 9, rem = k - 9 * ci;
        int kh = rem / 3;
        int w0 = wn * 32;
        int lo = 0, hi = 0;
        if (bx == 0 && kh == 0) { lo = w0; hi = min(w0 + 32, 56); }
        if (bx == 24 && kh == 2) { lo = max(w0, 8); hi = min(w0 + 32, 64); }
        for (int pl = lo; pl < hi; pl++) {
            uint32_t off = SWB((uint32_t)(krow * 256 + pl * 2));
            asm volatile("st.shared.u16 [%0], %1;" :: "r"(S + OFF_B + off),
                         "h"((unsigned short)0) : "memory");
        }
    };

    auto compute = [&](int s) {
        uint32_t S = abase + s * STAGE;
        uint32_t As = S + OFF_A, Bs = S + OFF_B;
        #pragma unroll
        for (int ks = 0; ks < 2; ks++) {
            uint32_t bh[2][4];
            #pragma unroll
            for (int nh = 0; nh < 2; nh++)
                LDSM4T(bh[nh], Bs + sB[nh] + (uint32_t)(ks * 4096));
            uint32_t ah[4][4];
            #pragma unroll
            for (int mi = 0; mi < 4; mi++)
                LDSM4(ah[mi], As + SWA(rA[mi] + (uint32_t)(ks * 32)));
            #pragma unroll
            for (int nh = 0; nh < 2; nh++)
                #pragma unroll
                for (int mi = 0; mi < 4; mi++)
                    #pragma unroll
                    for (int jn = 0; jn < 2; jn++)
                        MMA(acc[mi][nh * 2 + jn], ah[mi], bh[nh][jn * 2], bh[nh][jn * 2 + 1]);
        }
    };

    // ---- pipeline: 6 stages, one sync per 3-chunk window (R10/R13 interleaving) ----
    fill(0, 0); CP_COMMIT();
    fill(1, 1); CP_COMMIT();
    fill(2, 2); CP_COMMIT();

    for (int cw = 0; cw < NCHUNK; cw += WINDOW) {
        CP_WAIT(0);        // all outstanding fills (cw..cw+2) complete
        __syncthreads();   // visible to all warps; stages (cw-3..cw-1)%6 free
        #pragma unroll
        for (int u = 0; u < WINDOW; u++) {
            int c = cw + u;
            int s = c % NSTAGE;
            patch(s, c);
            compute(s);
            int f = c + WINDOW;
            if (f < NCHUNK) { fill(f % NSTAGE, f); CP_COMMIT(); }
        }
    }

    // ---- epilogue ----
    int r0 = wm * 64 + (lane >> 2);
    #pragma unroll
    for (int mi = 0; mi < 4; mi++) {
        int row = r0 + mi * 16;
        float b0 = bsm[row], b1 = bsm[row + 8];
        float* o0 = out + ((size_t)(b * COUT_ + coBase + row)) * HW_;
        float* o1 = o0 + 8 * HW_;
        #pragma unroll
        for (int j = 0; j < 4; j++) {
            int p = pBase + wn * 32 + j * 8 + (lane & 3) * 2;
            if (p < HW_) {
                float2 v0 = make_float2(acc[mi][j][0] + b0, acc[mi][j][1] + b0);
                float2 v1 = make_float2(acc[mi][j][2] + b1, acc[mi][j][3] + b1);
                *(float2*)(o0 + p) = v0;
                *(float2*)(o1 + p) = v1;
            }
        }
    }
}

// ------------------------- launch -------------------------
extern "C" void kernel_launch(void* const* d_in, const int* in_sizes, int n_in,
                              void* d_out, int out_size) {
    const float* x      = (const float*)d_in[0];
    const float* weight = (const float*)d_in[1];
    const float* bias   = (const float*)d_in[2];
    const float* fc1_w  = (const float*)d_in[3];
    const float* fc1_b  = (const float*)d_in[4];
    const float* fc2_w  = (const float*)d_in[5];
    const float* fc2_b  = (const float*)d_in[6];
    float* out = (float*)d_out;

    cudaFuncSetAttribute(conv_kernel,
                         cudaFuncAttributeMaxDynamicSharedMemorySize, DSMEM_BYTES);

    xsplit_kernel<<<dim3(CIN_, B_), 256>>>(x);
    attn_kernel<<<1, 128>>>(fc1_w, fc1_b, fc2_w, fc2_b);
    aggw_kernel<<<WPE_ / 4 / 256, 256>>>(weight);
    conv_kernel<<<dim3((HW_ + BN - 1) / BN, COUT_ / BM, B_), 256, DSMEM_BYTES>>>(bias, out);
}